// round 2
// baseline (speedup 1.0000x reference)
#include <cuda_runtime.h>
#include <cuda_bf16.h>
#include <cstdint>

#define E_  8
#define H_  1024
#define I_  2048
#define T_  1024

#define TM  128
#define TN  64
#define KB  16
#define KST (KB + 4)   // padded smem stride (20 floats = 80B, 16B aligned, conflict-free frags)

// ---------------- scratch (device globals; no allocation allowed) ----------------
__device__ int   g_cnt[E_];
__device__ int   g_tok[E_ * T_];
__device__ int   g_slot[E_ * T_];
__device__ float g_gate[E_ * T_];
__device__ float g_act[(size_t)E_ * T_ * I_];      // 64 MB
__device__ float g_ypart[(size_t)T_ * 2 * H_];     // 8 MB

// ---------------- PTX helpers ----------------
__device__ __forceinline__ void cp16(void* s, const void* g) {
    uint32_t sa = (uint32_t)__cvta_generic_to_shared(s);
    asm volatile("cp.async.cg.shared.global [%0], [%1], 16;\n" :: "r"(sa), "l"(g));
}
__device__ __forceinline__ void cp_commit() { asm volatile("cp.async.commit_group;\n"); }
__device__ __forceinline__ void cp_wait1()  { asm volatile("cp.async.wait_group 1;\n"); }
__device__ __forceinline__ void cp_wait0()  { asm volatile("cp.async.wait_group 0;\n"); }

__device__ __forceinline__ uint32_t f2tf(float f) {
    uint32_t u;
    asm("cvt.rna.tf32.f32 %0, %1;" : "=r"(u) : "f"(f));
    return u;
}
__device__ __forceinline__ void mma8(float c[4], const uint32_t a[4], const uint32_t b[2]) {
    asm volatile(
        "mma.sync.aligned.m16n8k8.row.col.f32.tf32.tf32.f32 "
        "{%0,%1,%2,%3}, {%4,%5,%6,%7}, {%8,%9}, {%0,%1,%2,%3};\n"
        : "+f"(c[0]), "+f"(c[1]), "+f"(c[2]), "+f"(c[3])
        : "r"(a[0]), "r"(a[1]), "r"(a[2]), "r"(a[3]), "r"(b[0]), "r"(b[1]));
}

// ---------------- router ----------------
__global__ void zero_cnt_kernel() {
    if (threadIdx.x < E_) g_cnt[threadIdx.x] = 0;
}

__global__ void router_kernel(const float* __restrict__ logits) {
    int t = blockIdx.x * blockDim.x + threadIdx.x;
    if (t >= T_) return;
    float l[E_];
    float mx = -1e30f;
#pragma unroll
    for (int e = 0; e < E_; e++) { l[e] = logits[t * E_ + e]; mx = fmaxf(mx, l[e]); }
    float p[E_];
#pragma unroll
    for (int e = 0; e < E_; e++) p[e] = __expf(l[e] - mx);
    int i1 = 0, i2 = -1;
    float v1 = p[0], v2 = -1.0f;
#pragma unroll
    for (int e = 1; e < E_; e++) {
        float pe = p[e];
        if (pe > v1) { v2 = v1; i2 = i1; v1 = pe; i1 = e; }
        else if (pe > v2) { v2 = pe; i2 = e; }
    }
    float inv = 1.0f / (v1 + v2);
    float w1 = v1 * inv, w2v = v2 * inv;
    int pos1 = atomicAdd(&g_cnt[i1], 1);
    g_tok[i1 * T_ + pos1] = t; g_slot[i1 * T_ + pos1] = 0; g_gate[i1 * T_ + pos1] = w1;
    int pos2 = atomicAdd(&g_cnt[i2], 1);
    g_tok[i2 * T_ + pos2] = t; g_slot[i2 * T_ + pos2] = 1; g_gate[i2 * T_ + pos2] = w2v;
}

// ---------------- GEMM1 + GLU activation (fused) ----------------
// act[row, n] = h_glu * sigmoid(1.702*h_glu) * (h_lin + 1),  n in [0, I_)
// h_glu = x[tok] . w13[e, n, :] + b13[e, n];  h_lin uses rows n + I_.
__global__ __launch_bounds__(256, 2) void gemm1_kernel(
    const float* __restrict__ x, const float* __restrict__ w13,
    const float* __restrict__ b13)
{
    int e = blockIdx.z;
    int cnt = g_cnt[e];
    int m0 = blockIdx.y * TM;
    if (m0 >= cnt) return;
    int n0 = blockIdx.x * TN;
    int tid = threadIdx.x;

    __shared__ float As[2][TM][KST];
    __shared__ float Bg[2][TN][KST];
    __shared__ float Bl[2][TN][KST];

    // A loader: each thread owns one row (tid>>1), 8 floats at col (tid&1)*8
    int arow = tid >> 1;
    int acol = (tid & 1) * 8;
    int mg = m0 + arow;
    int tok = (mg < cnt) ? g_tok[e * T_ + mg] : g_tok[e * T_];
    const float* aptr = x + (size_t)tok * H_ + acol;

    // B loaders: row tid>>2, 4 floats at col (tid&3)*4
    int brow = tid >> 2;
    int bcol = (tid & 3) * 4;
    const float* bgptr = w13 + ((size_t)e * 2 * I_ + (n0 + brow)) * H_ + bcol;
    const float* blptr = bgptr + (size_t)I_ * H_;

    float accG[2][4][4], accL[2][4][4];
#pragma unroll
    for (int i = 0; i < 2; i++)
#pragma unroll
        for (int j = 0; j < 4; j++)
#pragma unroll
            for (int k = 0; k < 4; k++) { accG[i][j][k] = 0.f; accL[i][j][k] = 0.f; }

    int lane = tid & 31, warp = tid >> 5;
    int wm = warp & 3, wn = warp >> 2;     // 4 x 2 warp grid, warp tile 32x32
    int gid = lane >> 2, tig = lane & 3;

    // stage 0
    cp16(&As[0][arow][acol], aptr);
    cp16(&As[0][arow][acol + 4], aptr + 4);
    cp16(&Bg[0][brow][bcol], bgptr);
    cp16(&Bl[0][brow][bcol], blptr);
    cp_commit();

    const int NK = H_ / KB;   // 64
    for (int kt = 0; kt < NK; ++kt) {
        int cur = kt & 1;
        if (kt + 1 < NK) {
            int nxt = cur ^ 1, k0 = (kt + 1) * KB;
            cp16(&As[nxt][arow][acol], aptr + k0);
            cp16(&As[nxt][arow][acol + 4], aptr + k0 + 4);
            cp16(&Bg[nxt][brow][bcol], bgptr + k0);
            cp16(&Bl[nxt][brow][bcol], blptr + k0);
            cp_commit();
            cp_wait1();
        } else {
            cp_wait0();
        }
        __syncthreads();
#pragma unroll
        for (int ks = 0; ks < 2; ++ks) {
            int kk = ks * 8;
            uint32_t a[2][4];
#pragma unroll
            for (int mi = 0; mi < 2; mi++) {
                int r = wm * 32 + mi * 16 + gid;
                a[mi][0] = f2tf(As[cur][r][kk + tig]);
                a[mi][1] = f2tf(As[cur][r + 8][kk + tig]);
                a[mi][2] = f2tf(As[cur][r][kk + tig + 4]);
                a[mi][3] = f2tf(As[cur][r + 8][kk + tig + 4]);
            }
#pragma unroll
            for (int ni = 0; ni < 4; ni++) {
                int n = wn * 32 + ni * 8 + gid;
                uint32_t bg[2], bl[2];
                bg[0] = __float_as_uint(Bg[cur][n][kk + tig]);
                bg[1] = __float_as_uint(Bg[cur][n][kk + tig + 4]);
                bl[0] = __float_as_uint(Bl[cur][n][kk + tig]);
                bl[1] = __float_as_uint(Bl[cur][n][kk + tig + 4]);
#pragma unroll
                for (int mi = 0; mi < 2; mi++) {
                    mma8(accG[mi][ni], a[mi], bg);
                    mma8(accL[mi][ni], a[mi], bl);
                }
            }
        }
        __syncthreads();
    }

    // epilogue: bias + GLU, write act rows (fp32)
    float bgv[4][2], blv[4][2];
#pragma unroll
    for (int ni = 0; ni < 4; ni++) {
        int n = n0 + wn * 32 + ni * 8 + tig * 2;
        bgv[ni][0] = __ldg(&b13[(size_t)e * 2 * I_ + n]);
        bgv[ni][1] = __ldg(&b13[(size_t)e * 2 * I_ + n + 1]);
        blv[ni][0] = __ldg(&b13[(size_t)e * 2 * I_ + I_ + n]);
        blv[ni][1] = __ldg(&b13[(size_t)e * 2 * I_ + I_ + n + 1]);
    }
    size_t actbase = (size_t)e * T_ * I_;
#pragma unroll
    for (int mi = 0; mi < 2; mi++) {
#pragma unroll
        for (int rr = 0; rr < 2; rr++) {
            int r = wm * 32 + mi * 16 + gid + rr * 8;
            int m = m0 + r;
            if (m >= cnt) continue;
            float* actrow = g_act + actbase + (size_t)m * I_;
#pragma unroll
            for (int ni = 0; ni < 4; ni++) {
                int n = n0 + wn * 32 + ni * 8 + tig * 2;
                float g0 = accG[mi][ni][rr * 2 + 0] + bgv[ni][0];
                float g1 = accG[mi][ni][rr * 2 + 1] + bgv[ni][1];
                float l0 = accL[mi][ni][rr * 2 + 0] + blv[ni][0];
                float l1 = accL[mi][ni][rr * 2 + 1] + blv[ni][1];
                float a0 = g0 * (1.f / (1.f + __expf(-1.702f * g0))) * (l0 + 1.0f);
                float a1 = g1 * (1.f / (1.f + __expf(-1.702f * g1))) * (l1 + 1.0f);
                *reinterpret_cast<float2*>(actrow + n) = make_float2(a0, a1);
            }
        }
    }
}

// ---------------- GEMM2: y = act @ w2^T + b2, scaled by gate, scattered ----------------
__global__ __launch_bounds__(256, 2) void gemm2_kernel(
    const float* __restrict__ w2, const float* __restrict__ b2)
{
    int e = blockIdx.z;
    int cnt = g_cnt[e];
    int m0 = blockIdx.y * TM;
    if (m0 >= cnt) return;
    int n0 = blockIdx.x * TN;
    int tid = threadIdx.x;

    __shared__ float As[2][TM][KST];
    __shared__ float Bs[2][TN][KST];

    int arow = tid >> 1;
    int acol = (tid & 1) * 8;
    const float* aptr = g_act + (size_t)(e * T_ + m0 + arow) * I_ + acol;
    int brow = tid >> 2;
    int bcol = (tid & 3) * 4;
    const float* bptr = w2 + ((size_t)e * H_ + (n0 + brow)) * I_ + bcol;

    float acc[2][4][4];
#pragma unroll
    for (int i = 0; i < 2; i++)
#pragma unroll
        for (int j = 0; j < 4; j++)
#pragma unroll
            for (int k = 0; k < 4; k++) acc[i][j][k] = 0.f;

    int lane = tid & 31, warp = tid >> 5;
    int wm = warp & 3, wn = warp >> 2;
    int gid = lane >> 2, tig = lane & 3;

    cp16(&As[0][arow][acol], aptr);
    cp16(&As[0][arow][acol + 4], aptr + 4);
    cp16(&Bs[0][brow][bcol], bptr);
    cp_commit();

    const int NK = I_ / KB;   // 128
    for (int kt = 0; kt < NK; ++kt) {
        int cur = kt & 1;
        if (kt + 1 < NK) {
            int nxt = cur ^ 1, k0 = (kt + 1) * KB;
            cp16(&As[nxt][arow][acol], aptr + k0);
            cp16(&As[nxt][arow][acol + 4], aptr + k0 + 4);
            cp16(&Bs[nxt][brow][bcol], bptr + k0);
            cp_commit();
            cp_wait1();
        } else {
            cp_wait0();
        }
        __syncthreads();
#pragma unroll
        for (int ks = 0; ks < 2; ++ks) {
            int kk = ks * 8;
            uint32_t a[2][4];
#pragma unroll
            for (int mi = 0; mi < 2; mi++) {
                int r = wm * 32 + mi * 16 + gid;
                a[mi][0] = f2tf(As[cur][r][kk + tig]);
                a[mi][1] = f2tf(As[cur][r + 8][kk + tig]);
                a[mi][2] = f2tf(As[cur][r][kk + tig + 4]);
                a[mi][3] = f2tf(As[cur][r + 8][kk + tig + 4]);
            }
#pragma unroll
            for (int ni = 0; ni < 4; ni++) {
                int n = wn * 32 + ni * 8 + gid;
                uint32_t b[2];
                b[0] = __float_as_uint(Bs[cur][n][kk + tig]);
                b[1] = __float_as_uint(Bs[cur][n][kk + tig + 4]);
#pragma unroll
                for (int mi = 0; mi < 2; mi++) mma8(acc[mi][ni], a[mi], b);
            }
        }
        __syncthreads();
    }

    float bv[4][2];
#pragma unroll
    for (int ni = 0; ni < 4; ni++) {
        int n = n0 + wn * 32 + ni * 8 + tig * 2;
        bv[ni][0] = __ldg(&b2[(size_t)e * H_ + n]);
        bv[ni][1] = __ldg(&b2[(size_t)e * H_ + n + 1]);
    }
#pragma unroll
    for (int mi = 0; mi < 2; mi++) {
#pragma unroll
        for (int rr = 0; rr < 2; rr++) {
            int r = wm * 32 + mi * 16 + gid + rr * 8;
            int m = m0 + r;
            if (m >= cnt) continue;
            int tok = g_tok[e * T_ + m];
            int slot = g_slot[e * T_ + m];
            float gt = g_gate[e * T_ + m];
            float* dst = g_ypart + (size_t)(tok * 2 + slot) * H_;
#pragma unroll
            for (int ni = 0; ni < 4; ni++) {
                int n = n0 + wn * 32 + ni * 8 + tig * 2;
                float v0 = (acc[mi][ni][rr * 2 + 0] + bv[ni][0]) * gt;
                float v1 = (acc[mi][ni][rr * 2 + 1] + bv[ni][1]) * gt;
                *reinterpret_cast<float2*>(dst + n) = make_float2(v0, v1);
            }
        }
    }
}

// ---------------- deterministic combine ----------------
__global__ void combine_kernel(float* __restrict__ out) {
    int i = blockIdx.x * blockDim.x + threadIdx.x;   // over T_*H_/4
    const int HV = H_ / 4;
    int t = i / HV;
    int h = i - t * HV;
    const float4* p0 = reinterpret_cast<const float4*>(g_ypart) + (size_t)(2 * t) * HV + h;
    const float4* p1 = p0 + HV;
    float4 a = *p0, b = *p1;
    reinterpret_cast<float4*>(out)[i] = make_float4(a.x + b.x, a.y + b.y, a.z + b.z, a.w + b.w);
}

// ---------------- launch ----------------
extern "C" void kernel_launch(void* const* d_in, const int* in_sizes, int n_in,
                              void* d_out, int out_size) {
    const float* x      = (const float*)d_in[0];
    const float* logits = (const float*)d_in[1];
    const float* w13    = (const float*)d_in[2];
    const float* w2     = (const float*)d_in[3];
    const float* b13    = (const float*)d_in[4];
    const float* b2     = (const float*)d_in[5];
    float* out = (float*)d_out;

    zero_cnt_kernel<<<1, 32>>>();
    router_kernel<<<T_ / 256, 256>>>(logits);

    dim3 g1(I_ / TN, T_ / TM, E_);   // 32 x 8 x 8 (most m-tiles early-exit)
    gemm1_kernel<<<g1, 256>>>(x, w13, b13);

    dim3 g2(H_ / TN, T_ / TM, E_);   // 16 x 8 x 8
    gemm2_kernel<<<g2, 256>>>(w2, b2);

    combine_kernel<<<(T_ * H_ / 4) / 256, 256>>>(out);
}